// round 1
// baseline (speedup 1.0000x reference)
#include <cuda_runtime.h>
#include <math.h>

#define NB 16
#define NA 720
#define ND 1024
#define NH 512
#define NW 512
#define PI_F 3.14159265358979323846f

// Filtered sinogram scratch (allocation-free rule: __device__ global). 47.2 MB.
__device__ float g_filtered[NB * NA * ND];

__device__ __forceinline__ float2 cmulf(float2 a, float2 b) {
    return make_float2(a.x * b.x - a.y * b.y, a.x * b.y + a.y * b.x);
}

// -------------------------------------------------------------------------
// Kernel 1: per-row ramp filter via radix-2 Stockham FFT in shared memory.
// One block = one sinogram row (b,a). 512 threads, 1 butterfly/thread/stage.
// ortho-fft * filt * ortho-ifft == default fft -> *filt -> ifft (scale 1/N).
// -------------------------------------------------------------------------
__global__ __launch_bounds__(512) void fbp_filter_kernel(
    const float* __restrict__ sino, const float* __restrict__ filt)
{
    __shared__ float2 bufA[ND];
    __shared__ float2 bufB[ND];
    __shared__ float2 tw[ND / 2];   // exp(-2*pi*i*k/N), k in [0,512)

    const int row = blockIdx.x;     // 0 .. NB*NA-1
    const int tid = threadIdx.x;    // 0 .. 511
    const float* src = sino + (size_t)row * ND;

    bufA[tid]       = make_float2(src[tid], 0.0f);
    bufA[tid + 512] = make_float2(src[tid + 512], 0.0f);
    {
        float sv, cv;
        sincosf((-2.0f * PI_F / ND) * (float)tid, &sv, &cv);
        tw[tid] = make_float2(cv, sv);
    }
    __syncthreads();

    float2* x = bufA;
    float2* y = bufB;

    // Forward FFT (Stockham DIF, natural order in/out)
    #pragma unroll
    for (int stage = 0; stage < 10; ++stage) {
        const int s  = 1 << stage;
        const int q  = tid & (s - 1);
        const int ps = tid - q;          // p * s  (twiddle index)
        float2 a = x[tid];               // x[q + s*p]
        float2 b = x[tid + 512];         // x[q + s*(p+m)]
        float2 w = tw[ps];
        float2 sum = make_float2(a.x + b.x, a.y + b.y);
        float2 dif = make_float2(a.x - b.x, a.y - b.y);
        y[2 * ps + q]     = sum;
        y[2 * ps + s + q] = cmulf(dif, w);
        __syncthreads();
        float2* t = x; x = y; y = t;
    }

    // Multiply by the (real) ramp filter
    {
        float f0 = filt[tid], f1 = filt[tid + 512];
        float2 a = x[tid];       a.x *= f0; a.y *= f0; x[tid]       = a;
        float2 b = x[tid + 512]; b.x *= f1; b.y *= f1; x[tid + 512] = b;
    }
    __syncthreads();

    // Inverse FFT (conjugated twiddles), scale 1/N at the end
    #pragma unroll
    for (int stage = 0; stage < 10; ++stage) {
        const int s  = 1 << stage;
        const int q  = tid & (s - 1);
        const int ps = tid - q;
        float2 a = x[tid];
        float2 b = x[tid + 512];
        float2 w = tw[ps]; w.y = -w.y;
        float2 sum = make_float2(a.x + b.x, a.y + b.y);
        float2 dif = make_float2(a.x - b.x, a.y - b.y);
        y[2 * ps + q]     = sum;
        y[2 * ps + s + q] = cmulf(dif, w);
        __syncthreads();
        float2* t = x; x = y; y = t;
    }

    const float invN = 1.0f / (float)ND;
    g_filtered[(size_t)row * ND + tid]       = x[tid].x * invN;
    g_filtered[(size_t)row * ND + tid + 512] = x[tid + 512].x * invN;
}

// -------------------------------------------------------------------------
// Kernel 2: backprojection. 16x16 pixel tile per block, 4 batches per thread
// (index math t/i0/w is batch-independent -> amortized 4x).
// Geometry: |px|,|py| <= 255.5 -> t in [150.2, 872.8], so i0 in [150,872]
// and i1 <= 873: the reference's 'valid' predicate is ALWAYS true and
// clamping is never triggered. No bounds checks needed.
// -------------------------------------------------------------------------
__global__ __launch_bounds__(256) void fbp_backproj_kernel(float* __restrict__ out)
{
    __shared__ float2 cs[NA];   // (cos, sin) per angle

    const int tid = threadIdx.x;
    for (int i = tid; i < NA; i += 256) {
        float sv, cv;
        sincosf((PI_F / (float)NA) * (float)i, &sv, &cv);
        cs[i] = make_float2(cv, sv);
    }
    __syncthreads();

    const int x = (blockIdx.x << 4) + (tid & 15);
    const int y = (blockIdx.y << 4) + (tid >> 4);
    const float px = (float)x - 0.5f * (float)(NW - 1);
    const float py = (float)y - 0.5f * (float)(NH - 1);

    const int b0 = blockIdx.z * 4;
    const float* base = g_filtered + (size_t)b0 * NA * ND;
    const int BS = NA * ND;     // batch stride in filtered sinogram

    float acc0 = 0.0f, acc1 = 0.0f, acc2 = 0.0f, acc3 = 0.0f;

    #pragma unroll 2
    for (int a = 0; a < NA; ++a) {
        float2 t2 = cs[a];
        float t = fmaf(px, t2.x, fmaf(py, t2.y, 0.5f * (float)(ND - 1)));
        float fi = floorf(t);
        int   i0 = (int)fi;
        float w  = t - fi;

        const float* r = base + a * ND + i0;
        float u00 = r[0],          u01 = r[1];
        float u10 = r[BS],         u11 = r[BS + 1];
        float u20 = r[2 * BS],     u21 = r[2 * BS + 1];
        float u30 = r[3 * BS],     u31 = r[3 * BS + 1];

        acc0 += fmaf(w, u01 - u00, u00);
        acc1 += fmaf(w, u11 - u10, u10);
        acc2 += fmaf(w, u21 - u20, u20);
        acc3 += fmaf(w, u31 - u30, u30);
    }

    const float scale = PI_F / (float)NA;
    const size_t pix = (size_t)y * NW + x;
    out[((size_t)(b0 + 0) * NH * NW) + pix] = acc0 * scale;
    out[((size_t)(b0 + 1) * NH * NW) + pix] = acc1 * scale;
    out[((size_t)(b0 + 2) * NH * NW) + pix] = acc2 * scale;
    out[((size_t)(b0 + 3) * NH * NW) + pix] = acc3 * scale;
}

extern "C" void kernel_launch(void* const* d_in, const int* in_sizes, int n_in,
                              void* d_out, int out_size)
{
    const float* sino = (const float*)d_in[0];   // (16, 720, 1024) fp32
    const float* filt = (const float*)d_in[1];   // (1024,) fp32
    float* out = (float*)d_out;                  // (16, 512, 512) fp32

    fbp_filter_kernel<<<NB * NA, 512>>>(sino, filt);

    dim3 grid(NW / 16, NH / 16, NB / 4);
    fbp_backproj_kernel<<<grid, 256>>>(out);
}